// round 4
// baseline (speedup 1.0000x reference)
#include <cuda_runtime.h>

#define NN 100000
#define EE 1600000
#define IN_CH 128
#define HID   64
#define OUTC  32
#define SCAN_B 1024

// Scratch (__device__ globals -- no cudaMalloc allowed)
__device__ int   g_deg [NN];            // degree incl. self-loop
__device__ int   g_off [NN];            // CSR row start (edges excl. self-loop)
__device__ int   g_cur [NN];            // fill cursor
__device__ int   g_bsum[(NN + SCAN_B - 1) / SCAN_B + 1];
__device__ int   g_csr [EE];            // src indices grouped by dst
__device__ float g_dinv[NN];
__device__ __align__(256) float g_hs1 [NN * HID];   // (x@W1)*dinv
__device__ __align__(256) float g_acc1[NN * HID];   // neighborhood sum (incl self)
__device__ __align__(256) float g_hs2 [NN * OUTC];
__device__ __align__(256) float g_acc2[NN * OUTC];

// ---------------------------------------------------------------- degree
__global__ void k_deg_init(int n) {
    int i = blockIdx.x * blockDim.x + threadIdx.x;
    if (i < n) g_deg[i] = 1;  // self loop
}
__global__ void k_deg_count(const int* __restrict__ dst, int e) {
    int i = blockIdx.x * blockDim.x + threadIdx.x;
    if (i < e) atomicAdd(&g_deg[dst[i]], 1);
}

// ---------------------------------------------------------------- scan (CSR offsets)
__global__ void k_scan1(int n) {
    __shared__ int sh[SCAN_B];
    int gid = blockIdx.x * SCAN_B + threadIdx.x;
    int v = (gid < n) ? (g_deg[gid] - 1) : 0;   // edges excluding self-loop
    sh[threadIdx.x] = v;
    __syncthreads();
#pragma unroll
    for (int off = 1; off < SCAN_B; off <<= 1) {
        int t = (threadIdx.x >= off) ? sh[threadIdx.x - off] : 0;
        __syncthreads();
        sh[threadIdx.x] += t;
        __syncthreads();
    }
    if (gid < n) g_off[gid] = sh[threadIdx.x] - v;          // exclusive
    if (threadIdx.x == SCAN_B - 1) g_bsum[blockIdx.x] = sh[SCAN_B - 1];
}
__global__ void k_scan2(int nb) {
    if (threadIdx.x == 0 && blockIdx.x == 0) {
        int s = 0;
        for (int i = 0; i < nb; i++) { int t = g_bsum[i]; g_bsum[i] = s; s += t; }
    }
}
__global__ void k_scan3(int n) {
    int gid = blockIdx.x * SCAN_B + threadIdx.x;
    if (gid < n) {
        g_off[gid] += g_bsum[blockIdx.x];
        g_dinv[gid] = rsqrtf((float)g_deg[gid]);
        g_cur[gid]  = 0;
    }
}
__global__ void k_fill(const int* __restrict__ src,
                       const int* __restrict__ dst, int e) {
    int i = blockIdx.x * blockDim.x + threadIdx.x;
    if (i < e) {
        int d = dst[i];
        int p = g_off[d] + atomicAdd(&g_cur[d], 1);
        g_csr[p] = src[i];
    }
}

// ---------------------------------------------------------------- GEMM1
// hs1[node] = (x[node] @ W1) * dinv[node]
__global__ void __launch_bounds__(128)
k_gemm1(const float* __restrict__ x, const float* __restrict__ W1, int n) {
    __shared__ float Ws[IN_CH * HID];  // 32 KB
    for (int i = threadIdx.x; i < IN_CH * HID; i += 128) Ws[i] = W1[i];
    __syncthreads();

    int node = blockIdx.x * 128 + threadIdx.x;
    if (node >= n) return;

    float acc[HID];
#pragma unroll
    for (int c = 0; c < HID; c++) acc[c] = 0.0f;

    const float4* x4 = reinterpret_cast<const float4*>(x) + node * (IN_CH / 4);
#pragma unroll 2
    for (int kc = 0; kc < IN_CH / 4; kc++) {
        float4 xv = __ldg(&x4[kc]);
        float xj[4] = {xv.x, xv.y, xv.z, xv.w};
#pragma unroll
        for (int j = 0; j < 4; j++) {
            const float4* wr = reinterpret_cast<const float4*>(Ws + (kc * 4 + j) * HID);
            float xs = xj[j];
#pragma unroll
            for (int c4 = 0; c4 < HID / 4; c4++) {
                float4 w = wr[c4];
                acc[c4 * 4 + 0] += xs * w.x;
                acc[c4 * 4 + 1] += xs * w.y;
                acc[c4 * 4 + 2] += xs * w.z;
                acc[c4 * 4 + 3] += xs * w.w;
            }
        }
    }

    float s = g_dinv[node];
    float4* o = reinterpret_cast<float4*>(g_hs1) + node * (HID / 4);
#pragma unroll
    for (int c4 = 0; c4 < HID / 4; c4++)
        o[c4] = make_float4(acc[c4 * 4 + 0] * s, acc[c4 * 4 + 1] * s,
                            acc[c4 * 4 + 2] * s, acc[c4 * 4 + 3] * s);
}

// ---------------------------------------------------------------- gather layer 1
// one warp per node; lane handles channels {lane, lane+32}
__global__ void k_gather1(int n) {
    int warp = (blockIdx.x * blockDim.x + threadIdx.x) >> 5;
    int lane = threadIdx.x & 31;
    if (warp >= n) return;

    float a0 = g_hs1[warp * HID + lane];        // self loop
    float a1 = g_hs1[warp * HID + 32 + lane];
    int beg = g_off[warp];
    int cnt = g_deg[warp] - 1;
    const int* cs = g_csr + beg;

    int j = 0;
    for (; j + 2 <= cnt; j += 2) {
        int s0 = cs[j], s1 = cs[j + 1];
        float b0 = g_hs1[s0 * HID + lane];
        float b1 = g_hs1[s0 * HID + 32 + lane];
        float c0 = g_hs1[s1 * HID + lane];
        float c1 = g_hs1[s1 * HID + 32 + lane];
        a0 += b0 + c0;
        a1 += b1 + c1;
    }
    if (j < cnt) {
        int s0 = cs[j];
        a0 += g_hs1[s0 * HID + lane];
        a1 += g_hs1[s0 * HID + 32 + lane];
    }
    g_acc1[warp * HID + lane]      = a0;
    g_acc1[warp * HID + 32 + lane] = a1;
}

// ---------------------------------------------------------------- GEMM2
// t = relu(dinv*acc1 + b1);  hs2 = (t @ W2) * dinv
__global__ void __launch_bounds__(128)
k_gemm2(const float* __restrict__ W2, const float* __restrict__ b1, int n) {
    __shared__ float Ws[HID * OUTC];  // 8 KB
    __shared__ float bs[HID];
    for (int i = threadIdx.x; i < HID * OUTC; i += 128) Ws[i] = W2[i];
    if (threadIdx.x < HID) bs[threadIdx.x] = b1[threadIdx.x];
    __syncthreads();

    int node = blockIdx.x * 128 + threadIdx.x;
    if (node >= n) return;

    float s = g_dinv[node];
    float acc[OUTC];
#pragma unroll
    for (int c = 0; c < OUTC; c++) acc[c] = 0.0f;

    const float4* a4 = reinterpret_cast<const float4*>(g_acc1) + node * (HID / 4);
#pragma unroll 2
    for (int k4 = 0; k4 < HID / 4; k4++) {
        float4 a = a4[k4];
        float t[4];
        t[0] = fmaxf(fmaf(s, a.x, bs[k4 * 4 + 0]), 0.0f);
        t[1] = fmaxf(fmaf(s, a.y, bs[k4 * 4 + 1]), 0.0f);
        t[2] = fmaxf(fmaf(s, a.z, bs[k4 * 4 + 2]), 0.0f);
        t[3] = fmaxf(fmaf(s, a.w, bs[k4 * 4 + 3]), 0.0f);
#pragma unroll
        for (int j = 0; j < 4; j++) {
            const float4* wr = reinterpret_cast<const float4*>(Ws + (k4 * 4 + j) * OUTC);
            float tv = t[j];
#pragma unroll
            for (int c4 = 0; c4 < OUTC / 4; c4++) {
                float4 w = wr[c4];
                acc[c4 * 4 + 0] += tv * w.x;
                acc[c4 * 4 + 1] += tv * w.y;
                acc[c4 * 4 + 2] += tv * w.z;
                acc[c4 * 4 + 3] += tv * w.w;
            }
        }
    }

    float4* o = reinterpret_cast<float4*>(g_hs2) + node * (OUTC / 4);
#pragma unroll
    for (int c4 = 0; c4 < OUTC / 4; c4++)
        o[c4] = make_float4(acc[c4 * 4 + 0] * s, acc[c4 * 4 + 1] * s,
                            acc[c4 * 4 + 2] * s, acc[c4 * 4 + 3] * s);
}

// ---------------------------------------------------------------- gather layer 2
// one warp per node; lane = channel
__global__ void k_gather2(int n) {
    int warp = (blockIdx.x * blockDim.x + threadIdx.x) >> 5;
    int lane = threadIdx.x & 31;
    if (warp >= n) return;

    float a0 = g_hs2[warp * OUTC + lane];       // self loop
    int beg = g_off[warp];
    int cnt = g_deg[warp] - 1;
    const int* cs = g_csr + beg;

    int j = 0;
    for (; j + 4 <= cnt; j += 4) {
        int s0 = cs[j], s1 = cs[j + 1], s2 = cs[j + 2], s3 = cs[j + 3];
        float b0 = g_hs2[s0 * OUTC + lane];
        float b1 = g_hs2[s1 * OUTC + lane];
        float b2 = g_hs2[s2 * OUTC + lane];
        float b3 = g_hs2[s3 * OUTC + lane];
        a0 += (b0 + b1) + (b2 + b3);
    }
    for (; j < cnt; j++) a0 += g_hs2[cs[j] * OUTC + lane];

    g_acc2[warp * OUTC + lane] = a0;
}

// ---------------------------------------------------------------- epilogue
__global__ void k_out(const float* __restrict__ b2, float* __restrict__ out, int n) {
    int idx = blockIdx.x * blockDim.x + threadIdx.x;
    if (idx >= n * OUTC) return;
    int node = idx >> 5;
    int c    = idx & 31;
    out[idx] = fmaf(g_dinv[node], g_acc2[idx], __ldg(&b2[c]));
}

// ----------------------------------------------------------------
extern "C" void kernel_launch(void* const* d_in, const int* in_sizes, int n_in,
                              void* d_out, int out_size) {
    const float* x   = (const float*)d_in[0];
    const int*   ei  = (const int*)d_in[1];   // int32! (JAX x64 disabled)
    const float* W1  = (const float*)d_in[2];
    const float* b1  = (const float*)d_in[3];
    const float* W2  = (const float*)d_in[4];
    const float* b2  = (const float*)d_in[5];
    float*       out = (float*)d_out;

    int n = in_sizes[0] / IN_CH;   // 100000
    int e = in_sizes[1] / 2;       // 1600000
    const int* src = ei;           // edge_index[0] (message sources)
    const int* dst = ei + e;       // edge_index[1] (message targets)

    int nscan = (n + SCAN_B - 1) / SCAN_B;

    k_deg_init <<<(n + 255) / 256, 256>>>(n);
    k_deg_count<<<(e + 255) / 256, 256>>>(dst, e);
    k_scan1    <<<nscan, SCAN_B>>>(n);
    k_scan2    <<<1, 32>>>(nscan);
    k_scan3    <<<nscan, SCAN_B>>>(n);
    k_fill     <<<(e + 255) / 256, 256>>>(src, dst, e);

    k_gemm1    <<<(n + 127) / 128, 128>>>(x, W1, n);
    k_gather1  <<<(n * 32 + 255) / 256, 256>>>(n);
    k_gemm2    <<<(n + 127) / 128, 128>>>(W2, b1, n);
    k_gather2  <<<(n * 32 + 255) / 256, 256>>>(n);
    k_out      <<<((n * OUTC) + 255) / 256, 256>>>(b2, out, n);
}

// round 5
// speedup vs baseline: 1.0278x; 1.0278x over previous
#include <cuda_runtime.h>

#define NN 100000
#define EE 1600000
#define IN_CH 128
#define HID   64
#define OUTC  32
#define SCAN_B 1024

// ---- packed f32x2 helpers (Blackwell) -------------------------------------
#define FMA2(d, a, b, c) \
    asm("fma.rn.f32x2 %0, %1, %2, %3;" : "=l"(d) : "l"(a), "l"(b), "l"(c))
#define PACK2_DUP(p, s) \
    asm("mov.b64 %0, {%1, %1};" : "=l"(p) : "f"(s))
#define UNPACK2(lo, hi, p) \
    asm("mov.b64 {%0, %1}, %2;" : "=f"(lo), "=f"(hi) : "l"(p))

// ---- scratch (__device__ globals; no cudaMalloc) ---------------------------
__device__ int   g_deg [NN];            // edge-in-degree (excl. self loop)
__device__ int   g_off [NN];            // CSR row start
__device__ int   g_cur [NN];            // fill cursor
__device__ int   g_bsum[128];
__device__ int   g_csr [EE];            // src indices grouped by dst
__device__ float g_dinv[NN];
__device__ __align__(256) float g_hs1 [NN * HID];   // x@W1, then *= dinv
__device__ __align__(256) float g_acc1[NN * HID];   // neighborhood sum
__device__ __align__(256) float g_hs2 [NN * OUTC];  // (relu(..)@W2)*dinv

// ---------------------------------------------------------------- init
__global__ void k_init(int n) {
    int i = blockIdx.x * blockDim.x + threadIdx.x;
    if (i < n) { g_deg[i] = 0; g_cur[i] = 0; }
}

// ---------------------------------------------------------------- hybrid:
// blocks [0,G1): hs1 = x @ W1 (raw, f32x2);  blocks [G1,...): degree count
__global__ void __launch_bounds__(128)
k_hybrid(const float* __restrict__ x, const float* __restrict__ W1,
         const int* __restrict__ dst, int n, int e, int G1) {
    __shared__ __align__(16) float Ws[IN_CH * HID];  // 32 KB

    if (blockIdx.x >= G1) {
        // ---- degree counting branch (4 edges/thread) ----
        int base = (blockIdx.x - G1) * 512;
#pragma unroll
        for (int k = 0; k < 4; k++) {
            int i = base + k * 128 + threadIdx.x;
            if (i < e) atomicAdd(&g_deg[dst[i]], 1);
        }
        return;
    }

    // ---- GEMM1 branch ----
    for (int i = threadIdx.x; i < IN_CH * HID; i += 128) Ws[i] = W1[i];
    __syncthreads();

    int node = blockIdx.x * 128 + threadIdx.x;
    if (node >= n) return;

    unsigned long long acc[HID / 2];
#pragma unroll
    for (int c = 0; c < HID / 2; c++) acc[c] = 0ULL;

    const float4* x4 = reinterpret_cast<const float4*>(x) + node * (IN_CH / 4);

#define GSTEP(XS, WR)                                                        \
    {                                                                        \
        unsigned long long xp; PACK2_DUP(xp, XS);                            \
        _Pragma("unroll")                                                    \
        for (int c = 0; c < 16; c++) {                                       \
            ulonglong2 w = (WR)[c];                                          \
            FMA2(acc[2 * c],     xp, w.x, acc[2 * c]);                       \
            FMA2(acc[2 * c + 1], xp, w.y, acc[2 * c + 1]);                   \
        }                                                                    \
    }

    for (int kc = 0; kc < IN_CH / 4; kc++) {
        float4 xv = __ldg(&x4[kc]);
        const ulonglong2* wrow =
            reinterpret_cast<const ulonglong2*>(Ws + kc * 4 * HID);
        GSTEP(xv.x, wrow);
        GSTEP(xv.y, wrow + 16);
        GSTEP(xv.z, wrow + 32);
        GSTEP(xv.w, wrow + 48);
    }
#undef GSTEP

    float4* o = reinterpret_cast<float4*>(g_hs1) + node * (HID / 4);
#pragma unroll
    for (int c = 0; c < 16; c++) {
        float f0, f1, f2, f3;
        UNPACK2(f0, f1, acc[2 * c]);
        UNPACK2(f2, f3, acc[2 * c + 1]);
        o[c] = make_float4(f0, f1, f2, f3);
    }
}

// ---------------------------------------------------------------- scan
__global__ void k_scan1(int n) {
    __shared__ int sh[SCAN_B];
    int gid = blockIdx.x * SCAN_B + threadIdx.x;
    int v = (gid < n) ? g_deg[gid] : 0;
    sh[threadIdx.x] = v;
    __syncthreads();
#pragma unroll
    for (int off = 1; off < SCAN_B; off <<= 1) {
        int t = (threadIdx.x >= off) ? sh[threadIdx.x - off] : 0;
        __syncthreads();
        sh[threadIdx.x] += t;
        __syncthreads();
    }
    if (gid < n) g_off[gid] = sh[threadIdx.x] - v;  // exclusive within block
    if (threadIdx.x == SCAN_B - 1) g_bsum[blockIdx.x] = sh[SCAN_B - 1];
}
__global__ void k_scan2(int nb) {   // nb <= 128, one block of 128
    __shared__ int sh[128];
    int v = (threadIdx.x < nb) ? g_bsum[threadIdx.x] : 0;
    sh[threadIdx.x] = v;
    __syncthreads();
#pragma unroll
    for (int off = 1; off < 128; off <<= 1) {
        int t = (threadIdx.x >= off) ? sh[threadIdx.x - off] : 0;
        __syncthreads();
        sh[threadIdx.x] += t;
        __syncthreads();
    }
    if (threadIdx.x < nb) g_bsum[threadIdx.x] = sh[threadIdx.x] - v;  // exclusive
}
__global__ void k_scan3(int n) {
    int gid = blockIdx.x * SCAN_B + threadIdx.x;
    if (gid < n) {
        g_off[gid] += g_bsum[blockIdx.x];
        g_dinv[gid] = rsqrtf((float)(g_deg[gid] + 1));  // +1 = self loop
    }
}

// ---------------------------------------------------------------- hybrid:
// blocks [0,F1): CSR fill;  blocks [F1,...): hs1 *= dinv[node]
__global__ void k_fill_scale(const int* __restrict__ src,
                             const int* __restrict__ dst, int e, int n, int F1) {
    if (blockIdx.x < F1) {
        int i = blockIdx.x * 256 + threadIdx.x;
        if (i < e) {
            int d = dst[i];
            int p = g_off[d] + atomicAdd(&g_cur[d], 1);
            g_csr[p] = src[i];
        }
    } else {
        int idx = (blockIdx.x - F1) * 256 + threadIdx.x;   // over n*16 float4s
        if (idx < n * (HID / 4)) {
            int node = idx >> 4;
            float s = g_dinv[node];
            float4* p = reinterpret_cast<float4*>(g_hs1) + idx;
            float4 v = *p;
            v.x *= s; v.y *= s; v.z *= s; v.w *= s;
            *p = v;
        }
    }
}

// ---------------------------------------------------------------- gather 1
// warp per node; coalesced index pre-load + shuffle broadcast
__global__ void k_gather1(int n) {
    int node = (blockIdx.x * blockDim.x + threadIdx.x) >> 5;
    int lane = threadIdx.x & 31;
    if (node >= n) return;

    const float* __restrict__ hs = g_hs1;
    float a0 = hs[node * HID + lane];        // self loop (already dinv-scaled)
    float a1 = hs[node * HID + 32 + lane];

    int beg = g_off[node];
    int cnt = g_deg[node];
    const int* cs = g_csr + beg;

    for (int base = 0; base < cnt; base += 32) {
        int rem = cnt - base;
        int m = rem < 32 ? rem : 32;
        int idx = (lane < m) ? cs[base + lane] : 0;
#pragma unroll 4
        for (int k = 0; k < m; k++) {
            int si = __shfl_sync(0xffffffffu, idx, k);
            const float* r = hs + si * HID;
            a0 += r[lane];
            a1 += r[32 + lane];
        }
    }
    g_acc1[node * HID + lane]      = a0;
    g_acc1[node * HID + 32 + lane] = a1;
}

// ---------------------------------------------------------------- GEMM2
// t = relu(dinv*acc1 + b1);  hs2 = (t @ W2) * dinv      (f32x2)
__global__ void __launch_bounds__(128)
k_gemm2(const float* __restrict__ W2, const float* __restrict__ b1, int n) {
    __shared__ __align__(16) float Ws[HID * OUTC];  // 8 KB
    __shared__ float bs[HID];
    for (int i = threadIdx.x; i < HID * OUTC; i += 128) Ws[i] = W2[i];
    if (threadIdx.x < HID) bs[threadIdx.x] = b1[threadIdx.x];
    __syncthreads();

    int node = blockIdx.x * 128 + threadIdx.x;
    if (node >= n) return;

    float s = g_dinv[node];
    unsigned long long acc[OUTC / 2];
#pragma unroll
    for (int c = 0; c < OUTC / 2; c++) acc[c] = 0ULL;

#define TSTEP(TS, WR)                                                        \
    {                                                                        \
        unsigned long long tp; PACK2_DUP(tp, TS);                            \
        _Pragma("unroll")                                                    \
        for (int c = 0; c < 8; c++) {                                        \
            ulonglong2 w = (WR)[c];                                          \
            FMA2(acc[2 * c],     tp, w.x, acc[2 * c]);                       \
            FMA2(acc[2 * c + 1], tp, w.y, acc[2 * c + 1]);                   \
        }                                                                    \
    }

    const float4* a4 = reinterpret_cast<const float4*>(g_acc1) + node * (HID / 4);
    for (int k4 = 0; k4 < HID / 4; k4++) {
        float4 a = a4[k4];
        float t0 = fmaxf(fmaf(s, a.x, bs[k4 * 4 + 0]), 0.0f);
        float t1 = fmaxf(fmaf(s, a.y, bs[k4 * 4 + 1]), 0.0f);
        float t2 = fmaxf(fmaf(s, a.z, bs[k4 * 4 + 2]), 0.0f);
        float t3 = fmaxf(fmaf(s, a.w, bs[k4 * 4 + 3]), 0.0f);
        const ulonglong2* wrow =
            reinterpret_cast<const ulonglong2*>(Ws + k4 * 4 * OUTC);
        TSTEP(t0, wrow);
        TSTEP(t1, wrow + 8);
        TSTEP(t2, wrow + 16);
        TSTEP(t3, wrow + 24);
    }
#undef TSTEP

    float4* o = reinterpret_cast<float4*>(g_hs2) + node * (OUTC / 4);
#pragma unroll
    for (int c = 0; c < 8; c++) {
        float f0, f1, f2, f3;
        UNPACK2(f0, f1, acc[2 * c]);
        UNPACK2(f2, f3, acc[2 * c + 1]);
        o[c] = make_float4(f0 * s, f1 * s, f2 * s, f3 * s);
    }
}

// ---------------------------------------------------------------- gather 2 + epilogue
// warp per node; out = dinv[node]*acc + b2
__global__ void k_gather2(const float* __restrict__ b2,
                          float* __restrict__ out, int n) {
    int node = (blockIdx.x * blockDim.x + threadIdx.x) >> 5;
    int lane = threadIdx.x & 31;
    if (node >= n) return;

    const float* __restrict__ hs = g_hs2;
    float a = hs[node * OUTC + lane];        // self loop (dinv-scaled)
    int beg = g_off[node];
    int cnt = g_deg[node];
    const int* cs = g_csr + beg;

    for (int base = 0; base < cnt; base += 32) {
        int rem = cnt - base;
        int m = rem < 32 ? rem : 32;
        int idx = (lane < m) ? cs[base + lane] : 0;
#pragma unroll 4
        for (int k = 0; k < m; k++) {
            int si = __shfl_sync(0xffffffffu, idx, k);
            a += hs[si * OUTC + lane];
        }
    }
    out[node * OUTC + lane] = fmaf(g_dinv[node], a, __ldg(&b2[lane]));
}

// ----------------------------------------------------------------
extern "C" void kernel_launch(void* const* d_in, const int* in_sizes, int n_in,
                              void* d_out, int out_size) {
    const float* x   = (const float*)d_in[0];
    const int*   ei  = (const int*)d_in[1];   // int32 (JAX default x64 disabled)
    const float* W1  = (const float*)d_in[2];
    const float* b1  = (const float*)d_in[3];
    const float* W2  = (const float*)d_in[4];
    const float* b2  = (const float*)d_in[5];
    float*       out = (float*)d_out;

    int n = in_sizes[0] / IN_CH;   // 100000
    int e = in_sizes[1] / 2;       // 1600000
    const int* src = ei;           // edge_index[0]
    const int* dst = ei + e;       // edge_index[1]

    int nscan = (n + SCAN_B - 1) / SCAN_B;          // 98
    int G1 = (n + 127) / 128;                       // gemm1 blocks
    int G2 = (e + 511) / 512;                       // degree blocks
    int F1 = (e + 255) / 256;                       // fill blocks
    int F2 = (n * (HID / 4) + 255) / 256;           // scale blocks

    k_init      <<<(n + 255) / 256, 256>>>(n);
    k_hybrid    <<<G1 + G2, 128>>>(x, W1, dst, n, e, G1);
    k_scan1     <<<nscan, SCAN_B>>>(n);
    k_scan2     <<<1, 128>>>(nscan);
    k_scan3     <<<nscan, SCAN_B>>>(n);
    k_fill_scale<<<F1 + F2, 256>>>(src, dst, e, n, F1);
    k_gather1   <<<(n * 32 + 255) / 256, 256>>>(n);
    k_gemm2     <<<G1, 128>>>(W2, b1, n);
    k_gather2   <<<(n * 32 + 255) / 256, 256>>>(b2, out, n);
}

// round 6
// speedup vs baseline: 1.0836x; 1.0543x over previous
#include <cuda_runtime.h>

#define NN 100000
#define EE 1600000
#define IN_CH 128
#define HID   64
#define OUTC  32
#define SCAN_B 1024

// ---- packed f32x2 helpers (Blackwell) -------------------------------------
#define FMA2(d, a, b, c) \
    asm("fma.rn.f32x2 %0, %1, %2, %3;" : "=l"(d) : "l"(a), "l"(b), "l"(c))
#define PACK2_DUP(p, s) \
    asm("mov.b64 %0, {%1, %1};" : "=l"(p) : "f"(s))
#define UNPACK2(lo, hi, p) \
    asm("mov.b64 {%0, %1}, %2;" : "=f"(lo), "=f"(hi) : "l"(p))

// ---- scratch (__device__ globals; no cudaMalloc) ---------------------------
__device__ int   g_deg [NN];            // edge-in-degree (excl. self loop)
__device__ int   g_off [NN];            // CSR row start
__device__ int   g_cur [NN];            // fill cursor
__device__ int   g_bsum[128];
__device__ int   g_csr [EE];            // src indices grouped by dst
__device__ float g_dinv[NN];
__device__ __align__(256) float g_hs1 [NN * HID];   // x@W1, then *= dinv
__device__ __align__(256) float g_acc1[NN * HID];   // neighborhood sum
__device__ __align__(256) float g_hs2 [NN * OUTC];  // (relu(..)@W2)*dinv

// ---------------------------------------------------------------- init
__global__ void k_init(int n) {
    int i = blockIdx.x * blockDim.x + threadIdx.x;
    if (i < n) { g_deg[i] = 0; g_cur[i] = 0; }
}

// ---------------------------------------------------------------- hybrid:
// blocks [0,G1): hs1 = x @ W1 (raw, f32x2);  blocks [G1,...): degree count
__global__ void __launch_bounds__(128)
k_hybrid(const float* __restrict__ x, const float* __restrict__ W1,
         const int* __restrict__ dst, int n, int e, int G1) {
    __shared__ __align__(16) float Ws[IN_CH * HID];  // 32 KB

    if (blockIdx.x >= G1) {
        int base = (blockIdx.x - G1) * 512;
#pragma unroll
        for (int k = 0; k < 4; k++) {
            int i = base + k * 128 + threadIdx.x;
            if (i < e) atomicAdd(&g_deg[dst[i]], 1);
        }
        return;
    }

    for (int i = threadIdx.x; i < IN_CH * HID; i += 128) Ws[i] = W1[i];
    __syncthreads();

    int node = blockIdx.x * 128 + threadIdx.x;
    if (node >= n) return;

    unsigned long long acc[HID / 2];
#pragma unroll
    for (int c = 0; c < HID / 2; c++) acc[c] = 0ULL;

    const float4* x4 = reinterpret_cast<const float4*>(x) + node * (IN_CH / 4);

#define GSTEP(XS, WR)                                                        \
    {                                                                        \
        unsigned long long xp; PACK2_DUP(xp, XS);                            \
        _Pragma("unroll")                                                    \
        for (int c = 0; c < 16; c++) {                                       \
            ulonglong2 w = (WR)[c];                                          \
            FMA2(acc[2 * c],     xp, w.x, acc[2 * c]);                       \
            FMA2(acc[2 * c + 1], xp, w.y, acc[2 * c + 1]);                   \
        }                                                                    \
    }

    for (int kc = 0; kc < IN_CH / 4; kc++) {
        float4 xv = __ldg(&x4[kc]);
        const ulonglong2* wrow =
            reinterpret_cast<const ulonglong2*>(Ws + kc * 4 * HID);
        GSTEP(xv.x, wrow);
        GSTEP(xv.y, wrow + 16);
        GSTEP(xv.z, wrow + 32);
        GSTEP(xv.w, wrow + 48);
    }
#undef GSTEP

    float4* o = reinterpret_cast<float4*>(g_hs1) + node * (HID / 4);
#pragma unroll
    for (int c = 0; c < 16; c++) {
        float f0, f1, f2, f3;
        UNPACK2(f0, f1, acc[2 * c]);
        UNPACK2(f2, f3, acc[2 * c + 1]);
        o[c] = make_float4(f0, f1, f2, f3);
    }
}

// ---------------------------------------------------------------- scan
__global__ void k_scan1(int n) {
    __shared__ int sh[SCAN_B];
    int gid = blockIdx.x * SCAN_B + threadIdx.x;
    int v = (gid < n) ? g_deg[gid] : 0;
    sh[threadIdx.x] = v;
    __syncthreads();
#pragma unroll
    for (int off = 1; off < SCAN_B; off <<= 1) {
        int t = (threadIdx.x >= off) ? sh[threadIdx.x - off] : 0;
        __syncthreads();
        sh[threadIdx.x] += t;
        __syncthreads();
    }
    if (gid < n) g_off[gid] = sh[threadIdx.x] - v;
    if (threadIdx.x == SCAN_B - 1) g_bsum[blockIdx.x] = sh[SCAN_B - 1];
}
__global__ void k_scan2(int nb) {
    __shared__ int sh[128];
    int v = (threadIdx.x < nb) ? g_bsum[threadIdx.x] : 0;
    sh[threadIdx.x] = v;
    __syncthreads();
#pragma unroll
    for (int off = 1; off < 128; off <<= 1) {
        int t = (threadIdx.x >= off) ? sh[threadIdx.x - off] : 0;
        __syncthreads();
        sh[threadIdx.x] += t;
        __syncthreads();
    }
    if (threadIdx.x < nb) g_bsum[threadIdx.x] = sh[threadIdx.x] - v;
}
__global__ void k_scan3(int n) {
    int gid = blockIdx.x * SCAN_B + threadIdx.x;
    if (gid < n) {
        g_off[gid] += g_bsum[blockIdx.x];
        g_dinv[gid] = rsqrtf((float)(g_deg[gid] + 1));  // +1 = self loop
    }
}

// ---------------------------------------------------------------- hybrid:
// blocks [0,F1): CSR fill;  blocks [F1,...): hs1 *= dinv[node]
__global__ void k_fill_scale(const int* __restrict__ src,
                             const int* __restrict__ dst, int e, int n, int F1) {
    if (blockIdx.x < F1) {
        int i = blockIdx.x * 256 + threadIdx.x;
        if (i < e) {
            int d = dst[i];
            int p = g_off[d] + atomicAdd(&g_cur[d], 1);
            g_csr[p] = src[i];
        }
    } else {
        int idx = (blockIdx.x - F1) * 256 + threadIdx.x;   // over n*16 float4s
        if (idx < n * (HID / 4)) {
            int node = idx >> 4;
            float s = g_dinv[node];
            float4* p = reinterpret_cast<float4*>(g_hs1) + idx;
            float4 v = *p;
            v.x *= s; v.y *= s; v.z *= s; v.w *= s;
            *p = v;
        }
    }
}

// ---------------------------------------------------------------- gather 1
// warp per node; 2 edges per step, float4 row loads.
// lanes 0-15: even edges, lanes 16-31: odd edges; channel group = lane & 15.
__global__ void __launch_bounds__(256) k_gather1(int n) {
    int node = (blockIdx.x * blockDim.x + threadIdx.x) >> 5;
    int lane = threadIdx.x & 31;
    if (node >= n) return;

    int g = lane & 15;
    int h = lane >> 4;
    const float4* __restrict__ hs = reinterpret_cast<const float4*>(g_hs1);

    float4 acc = make_float4(0.f, 0.f, 0.f, 0.f);

    int beg = g_off[node];
    int cnt = g_deg[node];
    const int* cs = g_csr + beg;

    for (int base = 0; base < cnt; base += 32) {
        int m = cnt - base; if (m > 32) m = 32;
        int idx = (lane < m) ? cs[base + lane] : 0;
        int steps = (m + 1) >> 1;
#pragma unroll 4
        for (int s = 0; s < steps; s++) {
            int eo = 2 * s + h;
            int si = __shfl_sync(0xffffffffu, idx, eo);
            if (eo < m) {
                float4 v = hs[si * (HID / 4) + g];
                acc.x += v.x; acc.y += v.y; acc.z += v.z; acc.w += v.w;
            }
        }
    }
    // combine even/odd halves
    acc.x += __shfl_xor_sync(0xffffffffu, acc.x, 16);
    acc.y += __shfl_xor_sync(0xffffffffu, acc.y, 16);
    acc.z += __shfl_xor_sync(0xffffffffu, acc.z, 16);
    acc.w += __shfl_xor_sync(0xffffffffu, acc.w, 16);

    if (lane < 16) {
        float4 sv = hs[node * (HID / 4) + g];   // self loop (dinv-scaled)
        acc.x += sv.x; acc.y += sv.y; acc.z += sv.z; acc.w += sv.w;
        reinterpret_cast<float4*>(g_acc1)[node * (HID / 4) + g] = acc;
    }
}

// ---------------------------------------------------------------- GEMM2
// t = relu(dinv*acc1 + b1);  hs2 = (t @ W2) * dinv      (f32x2)
__global__ void __launch_bounds__(128)
k_gemm2(const float* __restrict__ W2, const float* __restrict__ b1, int n) {
    __shared__ __align__(16) float Ws[HID * OUTC];  // 8 KB
    __shared__ float bs[HID];
    for (int i = threadIdx.x; i < HID * OUTC; i += 128) Ws[i] = W2[i];
    if (threadIdx.x < HID) bs[threadIdx.x] = b1[threadIdx.x];
    __syncthreads();

    int node = blockIdx.x * 128 + threadIdx.x;
    if (node >= n) return;

    float s = g_dinv[node];
    unsigned long long acc[OUTC / 2];
#pragma unroll
    for (int c = 0; c < OUTC / 2; c++) acc[c] = 0ULL;

#define TSTEP(TS, WR)                                                        \
    {                                                                        \
        unsigned long long tp; PACK2_DUP(tp, TS);                            \
        _Pragma("unroll")                                                    \
        for (int c = 0; c < 8; c++) {                                        \
            ulonglong2 w = (WR)[c];                                          \
            FMA2(acc[2 * c],     tp, w.x, acc[2 * c]);                       \
            FMA2(acc[2 * c + 1], tp, w.y, acc[2 * c + 1]);                   \
        }                                                                    \
    }

    const float4* a4 = reinterpret_cast<const float4*>(g_acc1) + node * (HID / 4);
    for (int k4 = 0; k4 < HID / 4; k4++) {
        float4 a = a4[k4];
        float t0 = fmaxf(fmaf(s, a.x, bs[k4 * 4 + 0]), 0.0f);
        float t1 = fmaxf(fmaf(s, a.y, bs[k4 * 4 + 1]), 0.0f);
        float t2 = fmaxf(fmaf(s, a.z, bs[k4 * 4 + 2]), 0.0f);
        float t3 = fmaxf(fmaf(s, a.w, bs[k4 * 4 + 3]), 0.0f);
        const ulonglong2* wrow =
            reinterpret_cast<const ulonglong2*>(Ws + k4 * 4 * OUTC);
        TSTEP(t0, wrow);
        TSTEP(t1, wrow + 8);
        TSTEP(t2, wrow + 16);
        TSTEP(t3, wrow + 24);
    }
#undef TSTEP

    float4* o = reinterpret_cast<float4*>(g_hs2) + node * (OUTC / 4);
#pragma unroll
    for (int c = 0; c < 8; c++) {
        float f0, f1, f2, f3;
        UNPACK2(f0, f1, acc[2 * c]);
        UNPACK2(f2, f3, acc[2 * c + 1]);
        o[c] = make_float4(f0 * s, f1 * s, f2 * s, f3 * s);
    }
}

// ---------------------------------------------------------------- gather 2 + epilogue
// warp per node; 4 edges per step, float4 row loads; out = dinv*acc + b2
__global__ void __launch_bounds__(256)
k_gather2(const float* __restrict__ b2, float* __restrict__ out, int n) {
    int node = (blockIdx.x * blockDim.x + threadIdx.x) >> 5;
    int lane = threadIdx.x & 31;
    if (node >= n) return;

    int g = lane & 7;
    int h = lane >> 3;          // 0..3
    const float4* __restrict__ hs = reinterpret_cast<const float4*>(g_hs2);

    float4 acc = make_float4(0.f, 0.f, 0.f, 0.f);

    int beg = g_off[node];
    int cnt = g_deg[node];
    const int* cs = g_csr + beg;

    for (int base = 0; base < cnt; base += 32) {
        int m = cnt - base; if (m > 32) m = 32;
        int idx = (lane < m) ? cs[base + lane] : 0;
        int steps = (m + 3) >> 2;
#pragma unroll 4
        for (int s = 0; s < steps; s++) {
            int eo = 4 * s + h;
            int si = __shfl_sync(0xffffffffu, idx, eo);
            if (eo < m) {
                float4 v = hs[si * (OUTC / 4) + g];
                acc.x += v.x; acc.y += v.y; acc.z += v.z; acc.w += v.w;
            }
        }
    }
    // combine 4 edge-groups (lanes g, g+8, g+16, g+24)
#pragma unroll
    for (int off = 16; off >= 8; off >>= 1) {
        acc.x += __shfl_xor_sync(0xffffffffu, acc.x, off);
        acc.y += __shfl_xor_sync(0xffffffffu, acc.y, off);
        acc.z += __shfl_xor_sync(0xffffffffu, acc.z, off);
        acc.w += __shfl_xor_sync(0xffffffffu, acc.w, off);
    }

    if (lane < 8) {
        float4 sv = hs[node * (OUTC / 4) + g];   // self loop
        float s = g_dinv[node];
        const float4* bb = reinterpret_cast<const float4*>(b2);
        float4 bv = __ldg(&bb[g]);
        float4 r;
        r.x = fmaf(s, acc.x + sv.x / s * s, 0.f);  // placeholder (rewritten below)
        // compute properly:
        r.x = fmaf(s, acc.x, 0.f);
        (void)r;
        float4 o;
        o.x = fmaf(s, acc.x + sv.x, bv.x);
        o.y = fmaf(s, acc.y + sv.y, bv.y);
        o.z = fmaf(s, acc.z + sv.z, bv.z);
        o.w = fmaf(s, acc.w + sv.w, bv.w);
        reinterpret_cast<float4*>(out)[node * (OUTC / 4) + g] = o;
    }
}

// ----------------------------------------------------------------
extern "C" void kernel_launch(void* const* d_in, const int* in_sizes, int n_in,
                              void* d_out, int out_size) {
    const float* x   = (const float*)d_in[0];
    const int*   ei  = (const int*)d_in[1];   // int32 (JAX default x64 disabled)
    const float* W1  = (const float*)d_in[2];
    const float* b1  = (const float*)d_in[3];
    const float* W2  = (const float*)d_in[4];
    const float* b2  = (const float*)d_in[5];
    float*       out = (float*)d_out;

    int n = in_sizes[0] / IN_CH;   // 100000
    int e = in_sizes[1] / 2;       // 1600000
    const int* src = ei;
    const int* dst = ei + e;

    int nscan = (n + SCAN_B - 1) / SCAN_B;
    int G1 = (n + 127) / 128;
    int G2 = (e + 511) / 512;
    int F1 = (e + 255) / 256;
    int F2 = (n * (HID / 4) + 255) / 256;

    k_init      <<<(n + 255) / 256, 256>>>(n);
    k_hybrid    <<<G1 + G2, 128>>>(x, W1, dst, n, e, G1);
    k_scan1     <<<nscan, SCAN_B>>>(n);
    k_scan2     <<<1, 128>>>(nscan);
    k_scan3     <<<nscan, SCAN_B>>>(n);
    k_fill_scale<<<F1 + F2, 256>>>(src, dst, e, n, F1);
    k_gather1   <<<(n * 32 + 255) / 256, 256>>>(n);
    k_gemm2     <<<G1, 128>>>(W2, b1, n);
    k_gather2   <<<(n * 32 + 255) / 256, 256>>>(b2, out, n);
}